// round 15
// baseline (speedup 1.0000x reference)
#include <cuda_runtime.h>
#include <cuda_fp16.h>
#include <math.h>
#include <stdint.h>

// Problem constants: B=4, Cin=Cout=256, H=W=64, K=3.
#define BATCH 4
#define CIN   256
#define COUT  256
#define HH    64
#define WWID  64
#define NPIX  16384
#define KTOT  2304

// Chunking: 16 channels -> 144 k -> 9 k16 steps per chunk, 16 chunks.
#define CCH    16
#define NSTEP  9
#define NCHUNK 16
#define NGS    (NCHUNK*NSTEP)   // 144 global k16-steps

#define NTHREADS 512            // 16 warps: (m-pair, nt-quad) grid 8x2

// smem: double-buffered B tile (single fp16), paired-nt groups.
// Group (s, ntp): 128 payload + 4 pad u32. 36 groups per buffer.
#define PGSTR  132
#define B_WORDS (NSTEP*4*PGSTR)         // 4752 u32 per buffer
#define SMEM_BYTES (2*B_WORDS*4)        // 38016

// W as single fp16, m16n8k16 A-fragment order:
// layout [gs(144)][mt(16)][lane(32)][reg(4)] u32 (fp16x2).
#define WFRAG (NGS*16*32*4)             // 294912
__device__ uint32_t g_whi[WFRAG];

__device__ __forceinline__ unsigned short f16b(float x) {
    __half h = __float2half_rn(x);
    return *reinterpret_cast<unsigned short*>(&h);
}

__device__ __forceinline__ void mma_f16(float* c, const uint32_t* a, const uint32_t* b) {
    asm volatile(
        "mma.sync.aligned.m16n8k16.row.col.f32.f16.f16.f32 "
        "{%0,%1,%2,%3}, {%4,%5,%6,%7}, {%8,%9}, {%0,%1,%2,%3};\n"
        : "+f"(c[0]), "+f"(c[1]), "+f"(c[2]), "+f"(c[3])
        : "r"(a[0]), "r"(a[1]), "r"(a[2]), "r"(a[3]), "r"(b[0]), "r"(b[1]));
}

// ---------------------------------------------------------------------------
// Kernel 0: W -> fp16, m16n8k16 A-fragment order.
// ---------------------------------------------------------------------------
__global__ void adaconv_prep_w(const float* __restrict__ w) {
    int t = blockIdx.x * 256 + threadIdx.x;
    if (t >= WFRAG) return;
    int i  = t & 3;
    int l  = (t >> 2) & 31;
    int mt = (t >> 7) & 15;
    int gs = t >> 11;
    int o = mt * 16 + (l >> 2) + (i & 1) * 8;
    int k = gs * 16 + (l & 3) * 2 + (i >> 1) * 8;
    float v0 = w[(size_t)o * KTOT + k];
    float v1 = w[(size_t)o * KTOT + k + 1];
    g_whi[t] = (uint32_t)f16b(v0) | ((uint32_t)f16b(v1) << 16);
}

// ---------------------------------------------------------------------------
// Kernel 1: fused scale + patch-build + fp16 mma.sync GEMM.
// Block: M=256 x 64 px (one row). 512 threads, 16 warps.
// Warp w: m-tiles {(w&7)*2, +1} x n-tiles {(w>>3)*4 .. +3}.
// B double-buffered, nt-paired: one LDS.128 = b-frags for 2 n-tiles.
// Per chunk: MMA(c) || build(c+1) -> one sync.
// ---------------------------------------------------------------------------
extern "C" __global__ void __launch_bounds__(NTHREADS, 2)
adaconv_main_kernel(const float* __restrict__ x,
                    const float* __restrict__ scales,
                    const float* __restrict__ bias,
                    float* __restrict__ out) {
    extern __shared__ uint32_t uB[];            // 2 x B_WORDS

    const int tid = threadIdx.x;
    const int bh  = blockIdx.x;                 // b*64 + r
    const int b   = bh >> 6;
    const int r   = bh & 63;

    // ---- per-pixel scale params (computed inline) ----
    const int p     = tid & 63;
    const int cpair = tid >> 6;                 // 0..7
    const int nt_b  = p >> 3;
    const int lf4   = ((p & 7) << 2) << 2;      // frag-lane-base * 4 words
    float f, gg;
    int   sc;
    {
        const float* sb = scales + b * HH * WWID;
        float sum = 0.0f;
#pragma unroll
        for (int jp = 0; jp < 3; jp++) {
            int q  = jp * 64 + r;
            int ho = q / 3;
            int kj = q - 3 * ho;
            int col = p + kj - 1;
            bool vc = ((unsigned)col < WWID);
#pragma unroll
            for (int ip = 0; ip < 3; ip++) {
                int row = ho + ip - 1;
                if (vc && (unsigned)row < HH)
                    sum += sb[row * WWID + col];
            }
        }
        float sm = sum / 9.0f;
        sc = (int)ceilf(sm);
        sc = min(3, max(1, sc));
        f  = sm / (float)sc;
        gg = 1.0f - f;
    }

    // ---- per-pixel tap geometry ----
    int   toff[3][3];
    float tmask[3][3];
#pragma unroll
    for (int jp = 0; jp < 3; jp++) {
        int q  = jp * 64 + r;
        int ho = q / 3;
        int kj = q - 3 * ho;
        int col = p + (kj - 1) * sc;
        bool vc = ((unsigned)col < WWID);
        int colc = min(max(col, 0), WWID - 1);
#pragma unroll
        for (int ip = 0; ip < 3; ip++) {
            int row = ho + (ip - 1) * sc;
            bool v = vc && ((unsigned)row < HH);
            int rowc = min(max(row, 0), HH - 1);
            toff[ip][jp]  = rowc * WWID + colc;
            tmask[ip][jp] = v ? 1.0f : 0.0f;
        }
    }

    const int w    = tid >> 5;                  // warp id
    const int l    = tid & 31;
    const int mt0  = (w & 7) * 2;               // first of 2 m-tiles
    const int ntg  = w >> 3;                    // 0..1 : n-tile quad

    float acc[2][4][4];                         // [mi][nt-local][frag]
#pragma unroll
    for (int mi = 0; mi < 2; mi++)
#pragma unroll
        for (int n = 0; n < 4; n++)
#pragma unroll
            for (int q = 0; q < 4; q++) acc[mi][n][q] = 0.0f;

    const float* xb = x + ((size_t)b * CIN << 12);
    const int aoff = mt0 * 128 + l * 4;         // within a gs segment (2048 words)

    // ---- builder: one channel-pair per thread into the given buffer ----
    auto build = [&](int chunk, uint32_t* dst) {
        float v[18];
#pragma unroll
        for (int cc = 0; cc < 2; cc++) {
            int c = 2 * cpair + cc;
            const float* xc = xb + ((size_t)(chunk * CCH + c) << 12);
            float t[3][3];
#pragma unroll
            for (int ip = 0; ip < 3; ip++)
#pragma unroll
                for (int jp = 0; jp < 3; jp++)
                    t[ip][jp] = xc[toff[ip][jp]] * tmask[ip][jp];
            float u[3][3];
#pragma unroll
            for (int ip = 0; ip < 3; ip++) {
                u[ip][0] = f * t[ip][0] + gg * t[ip][1];
                u[ip][1] = t[ip][1];
                u[ip][2] = gg * t[ip][1] + f * t[ip][2];
            }
            float* vd = v + cc * 9;
#pragma unroll
            for (int j = 0; j < 3; j++) {
                vd[j]     = f * u[0][j] + gg * u[1][j];
                vd[3 + j] = u[1][j];
                vd[6 + j] = gg * u[1][j] + f * u[2][j];
            }
        }
        // 9 word-pairs: k = 18*cpair + 2j (even), pp = (k&15)>>1.
        // word = (s*4 + nt/2)*PGSTR + (fraglane)*4 + (nt&1)*2 + (pp>>2),
        // fraglane = (p&7)*4 + (pp&3).
#pragma unroll
        for (int j = 0; j < 9; j++) {
            int k  = 18 * cpair + 2 * j;
            int s  = k >> 4;
            int pp = (k & 15) >> 1;
            int off = (s * 4 + (nt_b >> 1)) * PGSTR
                    + lf4 + ((pp & 3) << 2)
                    + ((nt_b & 1) << 1) + (pp >> 2);
            dst[off] = (uint32_t)f16b(v[2 * j])
                     | ((uint32_t)f16b(v[2 * j + 1]) << 16);
        }
    };

    // ---- prologue: build chunk 0 into buffer 0 ----
    build(0, uB);
    __syncthreads();

    // ---- main pipeline: MMA(c) then build(c+1) into the other buffer ----
    for (int chunk = 0; chunk < NCHUNK; chunk++) {
        const uint32_t* bufR = uB + (chunk & 1) * B_WORDS;
#pragma unroll 3
        for (int s = 0; s < NSTEP; s++) {
            int seg = (chunk * NSTEP + s) * 2048 + aoff;
            uint4 a0 = *(const uint4*)(g_whi + seg);
            uint4 a1 = *(const uint4*)(g_whi + seg + 128);
            uint32_t af0[4] = {a0.x, a0.y, a0.z, a0.w};
            uint32_t af1[4] = {a1.x, a1.y, a1.z, a1.w};
#pragma unroll
            for (int np = 0; np < 2; np++) {
                int ntp = ntg * 2 + np;
                uint4 bb = *(const uint4*)&bufR[(s * 4 + ntp) * PGSTR + l * 4];
                uint32_t be[2] = {bb.x, bb.y};   // even n-tile of the pair
                uint32_t bo[2] = {bb.z, bb.w};   // odd  n-tile of the pair
                mma_f16(acc[0][np * 2 + 0], af0, be);
                mma_f16(acc[0][np * 2 + 1], af0, bo);
                mma_f16(acc[1][np * 2 + 0], af1, be);
                mma_f16(acc[1][np * 2 + 1], af1, bo);
            }
        }
        if (chunk + 1 < NCHUNK)
            build(chunk + 1, uB + ((chunk + 1) & 1) * B_WORDS);
        __syncthreads();
    }

    // ---- epilogue ----
#pragma unroll
    for (int mi = 0; mi < 2; mi++) {
        int row0 = (mt0 + mi) * 16 + (l >> 2);
        int row1 = row0 + 8;
        float bz0 = bias[row0];
        float bz1 = bias[row1];
        size_t base0 = (((size_t)b * COUT + row0) * HH + r) * WWID;
        size_t base1 = (((size_t)b * COUT + row1) * HH + r) * WWID;
#pragma unroll
        for (int n = 0; n < 4; n++) {
            int nt = ntg * 4 + n;                // acc[mi][n] -> n-tile nt
            int col = nt * 8 + 2 * (l & 3);
            float2 v0 = {acc[mi][n][0] + bz0, acc[mi][n][1] + bz0};
            float2 v1 = {acc[mi][n][2] + bz1, acc[mi][n][3] + bz1};
            *(float2*)&out[base0 + col] = v0;
            *(float2*)&out[base1 + col] = v1;
        }
    }
}

// ---------------------------------------------------------------------------
// Entry point. Inputs by element count: x 4194304, scales 16384,
// weight 589824, bias 256. Output fp32.
// ---------------------------------------------------------------------------
extern "C" void kernel_launch(void* const* d_in, const int* in_sizes, int n_in,
                              void* d_out, int out_size) {
    const float *x = 0, *scales = 0, *weight = 0, *bias = 0;
    for (int i = 0; i < n_in; i++) {
        switch (in_sizes[i]) {
            case 4194304: x      = (const float*)d_in[i]; break;
            case 16384:   scales = (const float*)d_in[i]; break;
            case 589824:  weight = (const float*)d_in[i]; break;
            case 256:     bias   = (const float*)d_in[i]; break;
        }
    }
    float* out = (float*)d_out;

    cudaFuncSetAttribute(adaconv_main_kernel,
                         cudaFuncAttributeMaxDynamicSharedMemorySize, SMEM_BYTES);

    adaconv_prep_w<<<(WFRAG + 255) / 256, 256>>>(weight);

    dim3 grid(BATCH * HH);                      // 256 blocks
    adaconv_main_kernel<<<grid, NTHREADS, SMEM_BYTES>>>(x, scales, bias, out);
}

// round 16
// speedup vs baseline: 1.1697x; 1.1697x over previous
#include <cuda_runtime.h>
#include <cuda_fp16.h>
#include <math.h>
#include <stdint.h>

// Problem constants: B=4, Cin=Cout=256, H=W=64, K=3.
#define BATCH 4
#define CIN   256
#define COUT  256
#define HH    64
#define WWID  64
#define NPIX  16384
#define KTOT  2304

// Chunking: 16 channels -> 144 k -> 9 k16 steps per chunk, 16 chunks.
#define CCH    16
#define NSTEP  9
#define NCHUNK 16
#define NGS    (NCHUNK*NSTEP)   // 144 global k16-steps

#define NTHREADS 256            // 8 warps: 4 m-quads x 2 nt-quads, 4x4 tiles each

// smem: double-buffered B tile (single fp16), paired-nt groups.
// Group (s, ntp): 128 payload + 4 pad u32. 36 groups per buffer.
#define PGSTR  132
#define B_WORDS (NSTEP*4*PGSTR)         // 4752 u32 per buffer
#define SMEM_BYTES (2*B_WORDS*4)        // 38016

// W as single fp16, m16n8k16 A-fragment order:
// layout [gs(144)][mt(16)][lane(32)][reg(4)] u32 (fp16x2).
#define WFRAG (NGS*16*32*4)             // 294912
__device__ uint32_t g_whi[WFRAG];

__device__ __forceinline__ unsigned short f16b(float x) {
    __half h = __float2half_rn(x);
    return *reinterpret_cast<unsigned short*>(&h);
}

__device__ __forceinline__ void mma_f16(float* c, const uint32_t* a, const uint32_t* b) {
    asm volatile(
        "mma.sync.aligned.m16n8k16.row.col.f32.f16.f16.f32 "
        "{%0,%1,%2,%3}, {%4,%5,%6,%7}, {%8,%9}, {%0,%1,%2,%3};\n"
        : "+f"(c[0]), "+f"(c[1]), "+f"(c[2]), "+f"(c[3])
        : "r"(a[0]), "r"(a[1]), "r"(a[2]), "r"(a[3]), "r"(b[0]), "r"(b[1]));
}

// ---------------------------------------------------------------------------
// Kernel 0: W -> fp16, m16n8k16 A-fragment order.
// ---------------------------------------------------------------------------
__global__ void adaconv_prep_w(const float* __restrict__ w) {
    int t = blockIdx.x * 256 + threadIdx.x;
    if (t >= WFRAG) return;
    int i  = t & 3;
    int l  = (t >> 2) & 31;
    int mt = (t >> 7) & 15;
    int gs = t >> 11;
    int o = mt * 16 + (l >> 2) + (i & 1) * 8;
    int k = gs * 16 + (l & 3) * 2 + (i >> 1) * 8;
    float v0 = w[(size_t)o * KTOT + k];
    float v1 = w[(size_t)o * KTOT + k + 1];
    g_whi[t] = (uint32_t)f16b(v0) | ((uint32_t)f16b(v1) << 16);
}

// ---------------------------------------------------------------------------
// Kernel 1: fused scale + patch-build + fp16 mma.sync GEMM.
// Block: M=256 x 64 px (one row). 256 threads, 8 warps.
// Warp w: m-tiles {(w&3)*4 .. +3} x n-tiles {(w>>2)*4 .. +3}. acc 4x4x4.
// B double-buffered, nt-paired: one LDS.128 = b-frags for 2 n-tiles.
// Builder thread: pixel tid&63, 4 channels (2 channel-pairs).
// Per chunk: MMA(c) || build(c+1) -> one sync.
// ---------------------------------------------------------------------------
extern "C" __global__ void __launch_bounds__(NTHREADS, 2)
adaconv_main_kernel(const float* __restrict__ x,
                    const float* __restrict__ scales,
                    const float* __restrict__ bias,
                    float* __restrict__ out) {
    extern __shared__ uint32_t uB[];            // 2 x B_WORDS

    const int tid = threadIdx.x;
    const int bh  = blockIdx.x;                 // b*64 + r
    const int b   = bh >> 6;
    const int r   = bh & 63;

    // ---- per-pixel scale params (computed inline) ----
    const int p    = tid & 63;
    const int cq   = tid >> 6;                  // 0..3 : channel quad
    const int nt_b = p >> 3;
    const int lf4  = ((p & 7) << 2) << 2;       // frag-lane-base * 4 words
    float f, gg;
    int   sc;
    {
        const float* sb = scales + b * HH * WWID;
        float sum = 0.0f;
#pragma unroll
        for (int jp = 0; jp < 3; jp++) {
            int q  = jp * 64 + r;
            int ho = q / 3;
            int kj = q - 3 * ho;
            int col = p + kj - 1;
            bool vc = ((unsigned)col < WWID);
#pragma unroll
            for (int ip = 0; ip < 3; ip++) {
                int row = ho + ip - 1;
                if (vc && (unsigned)row < HH)
                    sum += sb[row * WWID + col];
            }
        }
        float sm = sum / 9.0f;
        sc = (int)ceilf(sm);
        sc = min(3, max(1, sc));
        f  = sm / (float)sc;
        gg = 1.0f - f;
    }

    // ---- per-pixel tap geometry ----
    int   toff[3][3];
    float tmask[3][3];
#pragma unroll
    for (int jp = 0; jp < 3; jp++) {
        int q  = jp * 64 + r;
        int ho = q / 3;
        int kj = q - 3 * ho;
        int col = p + (kj - 1) * sc;
        bool vc = ((unsigned)col < WWID);
        int colc = min(max(col, 0), WWID - 1);
#pragma unroll
        for (int ip = 0; ip < 3; ip++) {
            int row = ho + (ip - 1) * sc;
            bool v = vc && ((unsigned)row < HH);
            int rowc = min(max(row, 0), HH - 1);
            toff[ip][jp]  = rowc * WWID + colc;
            tmask[ip][jp] = v ? 1.0f : 0.0f;
        }
    }

    const int w    = tid >> 5;                  // warp id (0..7)
    const int l    = tid & 31;
    const int mt0  = (w & 3) * 4;               // first of 4 m-tiles
    const int ntg  = w >> 2;                    // 0..1 : n-tile quad

    float acc[4][4][4];                         // [mi][nt-local][frag]
#pragma unroll
    for (int mi = 0; mi < 4; mi++)
#pragma unroll
        for (int n = 0; n < 4; n++)
#pragma unroll
            for (int q = 0; q < 4; q++) acc[mi][n][q] = 0.0f;

    const float* xb = x + ((size_t)b * CIN << 12);
    const int aoff = mt0 * 128 + l * 4;         // within a gs segment (2048 words)

    // ---- builder: 2 channel-pairs (4 channels) per thread ----
    auto build = [&](int chunk, uint32_t* dst) {
#pragma unroll
        for (int cp2 = 0; cp2 < 2; cp2++) {
            int cpair = cq * 2 + cp2;           // 0..7
            float v[18];
#pragma unroll
            for (int cc = 0; cc < 2; cc++) {
                int c = 2 * cpair + cc;
                const float* xc = xb + ((size_t)(chunk * CCH + c) << 12);
                float t[3][3];
#pragma unroll
                for (int ip = 0; ip < 3; ip++)
#pragma unroll
                    for (int jp = 0; jp < 3; jp++)
                        t[ip][jp] = xc[toff[ip][jp]] * tmask[ip][jp];
                float u[3][3];
#pragma unroll
                for (int ip = 0; ip < 3; ip++) {
                    u[ip][0] = f * t[ip][0] + gg * t[ip][1];
                    u[ip][1] = t[ip][1];
                    u[ip][2] = gg * t[ip][1] + f * t[ip][2];
                }
                float* vd = v + cc * 9;
#pragma unroll
                for (int j = 0; j < 3; j++) {
                    vd[j]     = f * u[0][j] + gg * u[1][j];
                    vd[3 + j] = u[1][j];
                    vd[6 + j] = gg * u[1][j] + f * u[2][j];
                }
            }
            // 9 word-pairs: k = 18*cpair + 2j (even), pp = (k&15)>>1.
#pragma unroll
            for (int j = 0; j < 9; j++) {
                int k  = 18 * cpair + 2 * j;
                int s  = k >> 4;
                int pp = (k & 15) >> 1;
                int off = (s * 4 + (nt_b >> 1)) * PGSTR
                        + lf4 + ((pp & 3) << 2)
                        + ((nt_b & 1) << 1) + (pp >> 2);
                dst[off] = (uint32_t)f16b(v[2 * j])
                         | ((uint32_t)f16b(v[2 * j + 1]) << 16);
            }
        }
    };

    // ---- prologue: build chunk 0 into buffer 0 ----
    build(0, uB);
    __syncthreads();

    // ---- main pipeline: MMA(c) then build(c+1) into the other buffer ----
    for (int chunk = 0; chunk < NCHUNK; chunk++) {
        const uint32_t* bufR = uB + (chunk & 1) * B_WORDS;
#pragma unroll 3
        for (int s = 0; s < NSTEP; s++) {
            int seg = (chunk * NSTEP + s) * 2048 + aoff;
            uint32_t af[4][4];
#pragma unroll
            for (int mi = 0; mi < 4; mi++) {
                uint4 a = *(const uint4*)(g_whi + seg + mi * 128);
                af[mi][0] = a.x; af[mi][1] = a.y; af[mi][2] = a.z; af[mi][3] = a.w;
            }
#pragma unroll
            for (int np = 0; np < 2; np++) {
                int ntp = ntg * 2 + np;
                uint4 bb = *(const uint4*)&bufR[(s * 4 + ntp) * PGSTR + l * 4];
                uint32_t be[2] = {bb.x, bb.y};   // even n-tile of the pair
                uint32_t bo[2] = {bb.z, bb.w};   // odd  n-tile of the pair
#pragma unroll
                for (int mi = 0; mi < 4; mi++) {
                    mma_f16(acc[mi][np * 2 + 0], af[mi], be);
                    mma_f16(acc[mi][np * 2 + 1], af[mi], bo);
                }
            }
        }
        if (chunk + 1 < NCHUNK)
            build(chunk + 1, uB + ((chunk + 1) & 1) * B_WORDS);
        __syncthreads();
    }

    // ---- epilogue ----
#pragma unroll
    for (int mi = 0; mi < 4; mi++) {
        int row0 = (mt0 + mi) * 16 + (l >> 2);
        int row1 = row0 + 8;
        float bz0 = bias[row0];
        float bz1 = bias[row1];
        size_t base0 = (((size_t)b * COUT + row0) * HH + r) * WWID;
        size_t base1 = (((size_t)b * COUT + row1) * HH + r) * WWID;
#pragma unroll
        for (int n = 0; n < 4; n++) {
            int nt = ntg * 4 + n;                // acc[mi][n] -> n-tile nt
            int col = nt * 8 + 2 * (l & 3);
            float2 v0 = {acc[mi][n][0] + bz0, acc[mi][n][1] + bz0};
            float2 v1 = {acc[mi][n][2] + bz1, acc[mi][n][3] + bz1};
            *(float2*)&out[base0 + col] = v0;
            *(float2*)&out[base1 + col] = v1;
        }
    }
}

// ---------------------------------------------------------------------------
// Entry point. Inputs by element count: x 4194304, scales 16384,
// weight 589824, bias 256. Output fp32.
// ---------------------------------------------------------------------------
extern "C" void kernel_launch(void* const* d_in, const int* in_sizes, int n_in,
                              void* d_out, int out_size) {
    const float *x = 0, *scales = 0, *weight = 0, *bias = 0;
    for (int i = 0; i < n_in; i++) {
        switch (in_sizes[i]) {
            case 4194304: x      = (const float*)d_in[i]; break;
            case 16384:   scales = (const float*)d_in[i]; break;
            case 589824:  weight = (const float*)d_in[i]; break;
            case 256:     bias   = (const float*)d_in[i]; break;
        }
    }
    float* out = (float*)d_out;

    cudaFuncSetAttribute(adaconv_main_kernel,
                         cudaFuncAttributeMaxDynamicSharedMemorySize, SMEM_BYTES);

    adaconv_prep_w<<<(WFRAG + 255) / 256, 256>>>(weight);

    dim3 grid(BATCH * HH);                      // 256 blocks
    adaconv_main_kernel<<<grid, NTHREADS, SMEM_BYTES>>>(x, scales, bias, out);
}

// round 17
// speedup vs baseline: 1.2436x; 1.0632x over previous
#include <cuda_runtime.h>
#include <cuda_fp16.h>
#include <math.h>
#include <stdint.h>

// Problem constants: B=4, Cin=Cout=256, H=W=64, K=3.
#define BATCH 4
#define CIN   256
#define COUT  256
#define HH    64
#define WWID  64
#define NPIX  16384
#define KTOT  2304

// Chunking: 32 channels -> 288 k -> 18 k16 steps per chunk, 8 chunks.
#define CCH    32
#define NSTEP  18
#define NCHUNK 8
#define NGS    144              // 144 global k16-steps total

#define NTHREADS 256            // 8 warps: 4 m-quads x 2 nt-quads, 4x4 tiles each

// smem: double-buffered B tile (single fp16), paired-nt groups.
// Group (s, ntp): 128 payload + 4 pad u32. 72 groups per buffer.
#define PGSTR  132
#define B_WORDS (NSTEP*4*PGSTR)         // 9504 u32 per buffer
#define SMEM_BYTES (2*B_WORDS*4)        // 76032

// W as single fp16, m16n8k16 A-fragment order:
// layout [gs(144)][mt(16)][lane(32)][reg(4)] u32 (fp16x2).
#define WFRAG (NGS*16*32*4)             // 294912
__device__ uint32_t g_whi[WFRAG];

__device__ __forceinline__ unsigned short f16b(float x) {
    __half h = __float2half_rn(x);
    return *reinterpret_cast<unsigned short*>(&h);
}

__device__ __forceinline__ void mma_f16(float* c, const uint32_t* a, const uint32_t* b) {
    asm volatile(
        "mma.sync.aligned.m16n8k16.row.col.f32.f16.f16.f32 "
        "{%0,%1,%2,%3}, {%4,%5,%6,%7}, {%8,%9}, {%0,%1,%2,%3};\n"
        : "+f"(c[0]), "+f"(c[1]), "+f"(c[2]), "+f"(c[3])
        : "r"(a[0]), "r"(a[1]), "r"(a[2]), "r"(a[3]), "r"(b[0]), "r"(b[1]));
}

// ---------------------------------------------------------------------------
// Kernel 0: W -> fp16, m16n8k16 A-fragment order.
// ---------------------------------------------------------------------------
__global__ void adaconv_prep_w(const float* __restrict__ w) {
    int t = blockIdx.x * 256 + threadIdx.x;
    if (t >= WFRAG) return;
    int i  = t & 3;
    int l  = (t >> 2) & 31;
    int mt = (t >> 7) & 15;
    int gs = t >> 11;
    int o = mt * 16 + (l >> 2) + (i & 1) * 8;
    int k = gs * 16 + (l & 3) * 2 + (i >> 1) * 8;
    float v0 = w[(size_t)o * KTOT + k];
    float v1 = w[(size_t)o * KTOT + k + 1];
    g_whi[t] = (uint32_t)f16b(v0) | ((uint32_t)f16b(v1) << 16);
}

// ---------------------------------------------------------------------------
// Kernel 1: fused scale + patch-build + fp16 mma.sync GEMM.
// Block: M=256 x 64 px (one row). 256 threads, 8 warps.
// Warp w: m-tiles {(w&3)*4 .. +3} x n-tiles {(w>>2)*4 .. +3}. acc 4x4x4.
// B double-buffered (32-channel chunks); builder thread owns pixel tid&63 and
// 8 channels (4 channel-pairs), one pair fired after MMA steps 1/5/9/13 so
// its LDG latency hides under subsequent tensor issue. One sync per chunk.
// ---------------------------------------------------------------------------
extern "C" __global__ void __launch_bounds__(NTHREADS, 2)
adaconv_main_kernel(const float* __restrict__ x,
                    const float* __restrict__ scales,
                    const float* __restrict__ bias,
                    float* __restrict__ out) {
    extern __shared__ uint32_t uB[];            // 2 x B_WORDS

    const int tid = threadIdx.x;
    const int bh  = blockIdx.x;                 // b*64 + r
    const int b   = bh >> 6;
    const int r   = bh & 63;

    // ---- per-pixel scale params (computed inline) ----
    const int p    = tid & 63;
    const int cq   = tid >> 6;                  // 0..3 : channel-pair quad base
    const int nt_b = p >> 3;
    const int lf4  = ((p & 7) << 2) << 2;       // frag-lane-base * 4 words
    float f, gg;
    int   sc;
    {
        const float* sb = scales + b * HH * WWID;
        float sum = 0.0f;
#pragma unroll
        for (int jp = 0; jp < 3; jp++) {
            int q  = jp * 64 + r;
            int ho = q / 3;
            int kj = q - 3 * ho;
            int col = p + kj - 1;
            bool vc = ((unsigned)col < WWID);
#pragma unroll
            for (int ip = 0; ip < 3; ip++) {
                int row = ho + ip - 1;
                if (vc && (unsigned)row < HH)
                    sum += sb[row * WWID + col];
            }
        }
        float sm = sum / 9.0f;
        sc = (int)ceilf(sm);
        sc = min(3, max(1, sc));
        f  = sm / (float)sc;
        gg = 1.0f - f;
    }

    // ---- per-pixel tap geometry ----
    int   toff[3][3];
    float tmask[3][3];
#pragma unroll
    for (int jp = 0; jp < 3; jp++) {
        int q  = jp * 64 + r;
        int ho = q / 3;
        int kj = q - 3 * ho;
        int col = p + (kj - 1) * sc;
        bool vc = ((unsigned)col < WWID);
        int colc = min(max(col, 0), WWID - 1);
#pragma unroll
        for (int ip = 0; ip < 3; ip++) {
            int row = ho + (ip - 1) * sc;
            bool v = vc && ((unsigned)row < HH);
            int rowc = min(max(row, 0), HH - 1);
            toff[ip][jp]  = rowc * WWID + colc;
            tmask[ip][jp] = v ? 1.0f : 0.0f;
        }
    }

    const int w    = tid >> 5;                  // warp id (0..7)
    const int l    = tid & 31;
    const int mt0  = (w & 3) * 4;               // first of 4 m-tiles
    const int ntg  = w >> 2;                    // 0..1 : n-tile quad

    float acc[4][4][4];                         // [mi][nt-local][frag]
#pragma unroll
    for (int mi = 0; mi < 4; mi++)
#pragma unroll
        for (int n = 0; n < 4; n++)
#pragma unroll
            for (int q = 0; q < 4; q++) acc[mi][n][q] = 0.0f;

    const float* xb = x + ((size_t)b * CIN << 12);
    const int aoff = mt0 * 128 + l * 4;         // within a gs segment (2048 words)

    // ---- builder: one channel-pair (local index 0..15) into given buffer ----
    auto build_cpair = [&](int cpl, int chunk, uint32_t* dst) {
        float v[18];
#pragma unroll
        for (int cc = 0; cc < 2; cc++) {
            int c = 2 * cpl + cc;               // 0..31 within chunk
            const float* xc = xb + ((size_t)(chunk * CCH + c) << 12);
            float t[3][3];
#pragma unroll
            for (int ip = 0; ip < 3; ip++)
#pragma unroll
                for (int jp = 0; jp < 3; jp++)
                    t[ip][jp] = xc[toff[ip][jp]] * tmask[ip][jp];
            float u[3][3];
#pragma unroll
            for (int ip = 0; ip < 3; ip++) {
                u[ip][0] = f * t[ip][0] + gg * t[ip][1];
                u[ip][1] = t[ip][1];
                u[ip][2] = gg * t[ip][1] + f * t[ip][2];
            }
            float* vd = v + cc * 9;
#pragma unroll
            for (int j = 0; j < 3; j++) {
                vd[j]     = f * u[0][j] + gg * u[1][j];
                vd[3 + j] = u[1][j];
                vd[6 + j] = gg * u[1][j] + f * u[2][j];
            }
        }
        // 9 word-pairs: k = 18*cpl + 2j (even), s = k>>4 (0..17), pp = (k&15)>>1.
#pragma unroll
        for (int j = 0; j < 9; j++) {
            int k  = 18 * cpl + 2 * j;
            int s  = k >> 4;
            int pp = (k & 15) >> 1;
            int off = (s * 4 + (nt_b >> 1)) * PGSTR
                    + lf4 + ((pp & 3) << 2)
                    + ((nt_b & 1) << 1) + (pp >> 2);
            dst[off] = (uint32_t)f16b(v[2 * j])
                     | ((uint32_t)f16b(v[2 * j + 1]) << 16);
        }
    };

    // ---- prologue: build chunk 0 (4 channel-pairs) into buffer 0 ----
#pragma unroll
    for (int m = 0; m < 4; m++) build_cpair(cq * 4 + m, 0, uB);
    __syncthreads();

    // ---- main pipeline: MMA steps with builds interleaved at s=1,5,9,13 ----
    for (int chunk = 0; chunk < NCHUNK; chunk++) {
        const uint32_t* bufR = uB + (chunk & 1) * B_WORDS;
        uint32_t* bufW = uB + ((chunk + 1) & 1) * B_WORDS;
        const bool more = (chunk + 1 < NCHUNK);
#pragma unroll
        for (int s = 0; s < NSTEP; s++) {
            int seg = (chunk * NSTEP + s) * 2048 + aoff;
            uint32_t af[4][4];
#pragma unroll
            for (int mi = 0; mi < 4; mi++) {
                uint4 a = *(const uint4*)(g_whi + seg + mi * 128);
                af[mi][0] = a.x; af[mi][1] = a.y; af[mi][2] = a.z; af[mi][3] = a.w;
            }
#pragma unroll
            for (int np = 0; np < 2; np++) {
                int ntp = ntg * 2 + np;
                uint4 bb = *(const uint4*)&bufR[(s * 4 + ntp) * PGSTR + l * 4];
                uint32_t be[2] = {bb.x, bb.y};   // even n-tile of the pair
                uint32_t bo[2] = {bb.z, bb.w};   // odd  n-tile of the pair
#pragma unroll
                for (int mi = 0; mi < 4; mi++) {
                    mma_f16(acc[mi][np * 2 + 0], af[mi], be);
                    mma_f16(acc[mi][np * 2 + 1], af[mi], bo);
                }
            }
            if ((s & 3) == 1 && s < 16) {        // s = 1, 5, 9, 13
                if (more) build_cpair(cq * 4 + (s >> 2), chunk + 1, bufW);
            }
        }
        __syncthreads();
    }

    // ---- epilogue ----
#pragma unroll
    for (int mi = 0; mi < 4; mi++) {
        int row0 = (mt0 + mi) * 16 + (l >> 2);
        int row1 = row0 + 8;
        float bz0 = bias[row0];
        float bz1 = bias[row1];
        size_t base0 = (((size_t)b * COUT + row0) * HH + r) * WWID;
        size_t base1 = (((size_t)b * COUT + row1) * HH + r) * WWID;
#pragma unroll
        for (int n = 0; n < 4; n++) {
            int nt = ntg * 4 + n;                // acc[mi][n] -> n-tile nt
            int col = nt * 8 + 2 * (l & 3);
            float2 v0 = {acc[mi][n][0] + bz0, acc[mi][n][1] + bz0};
            float2 v1 = {acc[mi][n][2] + bz1, acc[mi][n][3] + bz1};
            *(float2*)&out[base0 + col] = v0;
            *(float2*)&out[base1 + col] = v1;
        }
    }
}

// ---------------------------------------------------------------------------
// Entry point. Inputs by element count: x 4194304, scales 16384,
// weight 589824, bias 256. Output fp32.
// ---------------------------------------------------------------------------
extern "C" void kernel_launch(void* const* d_in, const int* in_sizes, int n_in,
                              void* d_out, int out_size) {
    const float *x = 0, *scales = 0, *weight = 0, *bias = 0;
    for (int i = 0; i < n_in; i++) {
        switch (in_sizes[i]) {
            case 4194304: x      = (const float*)d_in[i]; break;
            case 16384:   scales = (const float*)d_in[i]; break;
            case 589824:  weight = (const float*)d_in[i]; break;
            case 256:     bias   = (const float*)d_in[i]; break;
        }
    }
    float* out = (float*)d_out;

    cudaFuncSetAttribute(adaconv_main_kernel,
                         cudaFuncAttributeMaxDynamicSharedMemorySize, SMEM_BYTES);

    adaconv_prep_w<<<(WFRAG + 255) / 256, 256>>>(weight);

    dim3 grid(BATCH * HH);                      // 256 blocks
    adaconv_main_kernel<<<grid, NTHREADS, SMEM_BYTES>>>(x, scales, bias, out);
}